// round 10
// baseline (speedup 1.0000x reference)
#include <cuda_runtime.h>
#include <cuda_fp16.h>
#include <cstdint>
#include <cstddef>

// ===========================================================================
// feature_embedding on GB300 (base compute_103: mma.sync fp16 tensor cores).
// Round 10: FUSED kernel — gcn mainloop + code/gate gemms + combine in one
// kernel; epilogue kernel and H16 global round-trip eliminated.
//  B=4, N=2048, DEST=64, NET=256, INPUT=448
// ===========================================================================

namespace {
constexpr int kB     = 4;
constexpr int kN     = 2048;
constexpr int kINPUT = 448;
constexpr int BM     = 128;
constexpr int BK     = 64;           // k per iter (4 x m16n8k16)
constexpr int SB     = 3;            // B cp.async stages
constexpr int NUM_K  = kN / BK;      // 32
constexpr int TILE_A16 = BM * BK * 2;            // 16 KB fp16 A tile
constexpr int TILE_B16 = 128 * BK * 2;           // 16 KB fp16 B tile
constexpr int A_REGION = 2 * TILE_A16;           // A double buffer 32 KB
constexpr int MAIN_REGION = A_REGION + SB * TILE_B16;   // 80 KB (1920 B pad)

// epilogue smem offsets (bytes from smem base)
constexpr int oH  = 0;               // H16 tile 128 x 272B (overlaps A/B, used after mainloop)
constexpr int oWc = 81920;           // WcT      64 x 272B  (prefetched at start)
constexpr int oS  = 99328;           // stat16  128 x 528B  (prefetched at start)
constexpr int oWe = 166912;          // WeT      64 x 528B  (prefetched at start)
constexpr int SMEM_TOTAL = 200704;   // 196 KB -> 1 CTA/SM
}

// scratch
__device__ __align__(1024) __half g_Bt    [(size_t)kB * 128 * kN];  // structT fp16
__device__ __align__(1024) __half g_stat16[(size_t)kB * kN * 256];  // stat fp16
__device__ __align__(256)  __half g_WcT   [2 * 64 * 128];           // [mat][n][k]
__device__ __align__(256)  __half g_WeT   [128 * 256];              // [n][k]

// ---------------------------------------------------------------------------
// helpers
// ---------------------------------------------------------------------------
__device__ __forceinline__ uint32_t smem_u32(const void* p) {
    uint32_t a;
    asm("{ .reg .u64 t; cvta.to.shared.u64 t, %1; cvt.u32.u64 %0, t; }"
        : "=r"(a) : "l"(p));
    return a;
}
__device__ __forceinline__ void cp_async16(uint32_t dst, const void* src) {
    asm volatile("cp.async.cg.shared.global [%0], [%1], 16;"
                 :: "r"(dst), "l"(src) : "memory");
}
__device__ __forceinline__ void cp_commit() {
    asm volatile("cp.async.commit_group;" ::: "memory");
}
template <int N>
__device__ __forceinline__ void cp_wait() {
    asm volatile("cp.async.wait_group %0;" :: "n"(N) : "memory");
}
__device__ __forceinline__ uint32_t lds_u32(uint32_t addr) {
    uint32_t v;
    asm volatile("ld.shared.b32 %0, [%1];" : "=r"(v) : "r"(addr));
    return v;
}
__device__ __forceinline__ void ldsm_x4(uint32_t r[4], uint32_t addr) {
    asm volatile("ldmatrix.sync.aligned.m8n8.x4.shared.b16 {%0,%1,%2,%3}, [%4];"
                 : "=r"(r[0]), "=r"(r[1]), "=r"(r[2]), "=r"(r[3]) : "r"(addr));
}
__device__ __forceinline__ void sts_u32(uint32_t addr, uint32_t v) {
    asm volatile("st.shared.b32 [%0], %1;" :: "r"(addr), "r"(v) : "memory");
}
__device__ __forceinline__ void sts_v4(uint32_t addr, uint32_t x, uint32_t y,
                                       uint32_t z, uint32_t w) {
    asm volatile("st.shared.v4.b32 [%0], {%1,%2,%3,%4};"
                 :: "r"(addr), "r"(x), "r"(y), "r"(z), "r"(w) : "memory");
}
__device__ __forceinline__ uint32_t pack_h2(float lo, float hi) {
    __half2 h = __floats2half2_rn(lo, hi);
    return *reinterpret_cast<uint32_t*>(&h);
}
__device__ __forceinline__ void mma_f16(float c[4], const uint32_t a[4],
                                        const uint32_t b[2]) {
    asm volatile(
        "mma.sync.aligned.m16n8k16.row.col.f32.f16.f16.f32 "
        "{%0,%1,%2,%3}, {%4,%5,%6,%7}, {%8,%9}, {%0,%1,%2,%3};"
        : "+f"(c[0]), "+f"(c[1]), "+f"(c[2]), "+f"(c[3])
        : "r"(a[0]), "r"(a[1]), "r"(a[2]), "r"(a[3]), "r"(b[0]), "r"(b[1]));
}

// ---------------------------------------------------------------------------
// Prep (single launch): blocks [0,1024) transpose struct -> g_Bt fp16;
// blocks [1024,1536) convert stat + weights.
// ---------------------------------------------------------------------------
__global__ void __launch_bounds__(256) prep_all(
    const float* __restrict__ nfeat,
    const float* __restrict__ Wf, const float* __restrict__ Wb,
    const float* __restrict__ We) {
    const int bx = blockIdx.x;
    if (bx < 1024) {
        __shared__ float t[32][33];
        const int b  = bx >> 8;
        const int f0 = ((bx >> 6) & 3) * 32;
        const int n0 = (bx & 63) * 32;
        const int tx = threadIdx.x & 31;
        const int ty = threadIdx.x >> 5;
#pragma unroll
        for (int j = 0; j < 32; j += 8)
            t[ty + j][tx] = nfeat[((size_t)(b * kN + n0 + ty + j)) * kINPUT + 64 + f0 + tx];
        __syncthreads();
#pragma unroll
        for (int j = 0; j < 32; j += 8)
            g_Bt[((size_t)b * 128 + f0 + ty + j) * kN + n0 + tx] =
                __float2half_rn(t[tx][ty + j]);
    } else {
        const int t = (bx - 1024) * 256 + threadIdx.x;   // 0..131071
        for (int i = t; i < kB * kN * 64; i += 131072) { // stat fp32 -> fp16
            const int row = i >> 6, c4 = i & 63;
            const float4 v = *(const float4*)(nfeat + (size_t)row * kINPUT + 192 + c4 * 4);
            uint32_t* d = reinterpret_cast<uint32_t*>(g_stat16 + (size_t)row * 256 + c4 * 4);
            d[0] = pack_h2(v.x, v.y);
            d[1] = pack_h2(v.z, v.w);
        }
        if (t < 128 * 256) {      // WeT
            const int n = t >> 8, k = t & 255;
            g_WeT[t] = __float2half_rn(We[k * 128 + n]);
        }
        if (t < 64 * 128) {       // WcT (both mats)
            const int n = t >> 7, k = t & 127;
            g_WcT[t]        = __float2half_rn(Wf[k * 64 + n]);
            g_WcT[8192 + t] = __float2half_rn(Wb[k * 64 + n]);
        }
    }
}

// ---------------------------------------------------------------------------
// Fused kernel: grid (16, 4, 2) = (m-tile, batch, mat); 256 threads (8 warps).
// Phase 1: H = adj_tile @ structT  (mainloop, ldmatrix + mma, 32 iters)
// Phase 2: code = H @ WcT[mat]; gate = sigmoid(stat @ WeT[mat*64:+64] + be);
//          out[:, mat*64:+64] = (code + bias) * dyn * gate
// stat/Wc/We tiles prefetched via leading cp.async group (hidden by mainloop).
// ---------------------------------------------------------------------------
__global__ void __launch_bounds__(256, 1) fused_kernel(
    const float* __restrict__ adjF, const float* __restrict__ adjB,
    const float* __restrict__ nfeat,
    const float* __restrict__ bfv, const float* __restrict__ bbv,
    const float* __restrict__ be,  float* __restrict__ out) {
    extern __shared__ char smem[];
    const uint32_t sb  = smem_u32(smem);
    const uint32_t sbA = sb;                             // A16: 2 x 16 KB
    const uint32_t sbB = sb + A_REGION;                  // B16: 3 x 16 KB

    const int tid  = threadIdx.x;
    const int warp = tid >> 5;
    const int lane = tid & 31;
    const int lr   = lane >> 2;
    const int lc   = lane & 3;
    const int wm   = (warp >> 2) * 64;
    const int wn   = (warp & 3) * 32;

    const int m0  = blockIdx.x * BM;
    const int b   = blockIdx.y;
    const int mat = blockIdx.z;
    const float* adj = mat ? adjB : adjF;
    const int r0g = b * kN + m0;         // global row base

    // ---- leading prefetch group: stat16 / WeT / WcT tiles ----
    for (int idx = tid; idx < 4096; idx += 256) {        // stat16 128x256
        const int row = idx >> 5, v = idx & 31;
        cp_async16(sb + oS + row * 528 + v * 16,
                   g_stat16 + ((size_t)(r0g + row)) * 256 + v * 8);
    }
    for (int idx = tid; idx < 2048; idx += 256) {        // WeT slice 64x256
        const int row = idx >> 5, v = idx & 31;
        cp_async16(sb + oWe + row * 528 + v * 16,
                   g_WeT + ((size_t)(mat * 64 + row)) * 256 + v * 8);
    }
    for (int idx = tid; idx < 1024; idx += 256) {        // WcT 64x128
        const int row = idx >> 4, v = idx & 15;
        cp_async16(sb + oWc + row * 272 + v * 16,
                   g_WcT + mat * 64 * 128 + row * 128 + v * 8);
    }
    cp_commit();

    // ---- loader geometry: 4 x 16B fp16 blocks per thread (A and B) ----
    const float*  srcA[4];
    const __half* srcB[4];
    uint32_t dstAB[4];
#pragma unroll
    for (int q = 0; q < 4; ++q) {
        const int idx = q * 256 + tid;
        const int row = idx >> 3;
        const int vec = idx & 7;
        srcA[q] = adj  + ((size_t)(r0g + row)) * kN + vec * 8;
        srcB[q] = g_Bt + ((size_t)(b * 128 + row)) * kN + vec * 8;
        dstAB[q] = (uint32_t)(row * 128 + ((vec ^ (row & 7)) << 4));
    }

    // ldmatrix per-lane base addresses (ks = 0)
    const int g  = lane >> 3;
    const int tr = lane & 7;
    uint32_t aLdsm[4];
#pragma unroll
    for (int mf = 0; mf < 4; ++mf) {
        const int row = wm + mf * 16 + (g & 1) * 8 + tr;
        aLdsm[mf] = (uint32_t)(row * 128 + (((g >> 1) ^ (row & 7)) << 4));
    }
    uint32_t bLdsm[2];
#pragma unroll
    for (int p = 0; p < 2; ++p) {
        const int row = wn + p * 16 + (g >> 1) * 8 + tr;
        bLdsm[p] = (uint32_t)(row * 128 + (((g & 1) ^ (row & 7)) << 4));
    }

    float c[4][4][4];
#pragma unroll
    for (int mf = 0; mf < 4; ++mf)
#pragma unroll
        for (int nb = 0; nb < 4; ++nb)
#pragma unroll
            for (int r = 0; r < 4; ++r) c[mf][nb][r] = 0.0f;

    // ---- B prologue ----
#pragma unroll
    for (int s = 0; s < SB - 1; ++s) {
#pragma unroll
        for (int q = 0; q < 4; ++q)
            cp_async16(sbB + s * TILE_B16 + dstAB[q], srcB[q] + s * BK);
        cp_commit();
    }
    float4 rA[4][2];
#pragma unroll
    for (int q = 0; q < 4; ++q) {            // A(0) -> regs
        rA[q][0] = *(const float4*)(srcA[q]);
        rA[q][1] = *(const float4*)(srcA[q] + 4);
    }
#pragma unroll
    for (int q = 0; q < 4; ++q)              // STS A(0) -> slot 0
        sts_v4(sbA + dstAB[q],
               pack_h2(rA[q][0].x, rA[q][0].y), pack_h2(rA[q][0].z, rA[q][0].w),
               pack_h2(rA[q][1].x, rA[q][1].y), pack_h2(rA[q][1].z, rA[q][1].w));
#pragma unroll
    for (int q = 0; q < 4; ++q) {            // A(1) -> regs
        rA[q][0] = *(const float4*)(srcA[q] + BK);
        rA[q][1] = *(const float4*)(srcA[q] + BK + 4);
    }

    // ---- mainloop: ONE sync per iteration, 32 iterations ----
    for (int i = 0; i < NUM_K; ++i) {
        cp_wait<SB - 2>();
        __syncthreads();

        if (i + 1 < NUM_K) {
            const uint32_t aNext = sbA + (uint32_t)(((i + 1) & 1) * TILE_A16);
#pragma unroll
            for (int q = 0; q < 4; ++q)
                sts_v4(aNext + dstAB[q],
                       pack_h2(rA[q][0].x, rA[q][0].y), pack_h2(rA[q][0].z, rA[q][0].w),
                       pack_h2(rA[q][1].x, rA[q][1].y), pack_h2(rA[q][1].z, rA[q][1].w));
        }
        if (i + 2 < NUM_K) {
            const int kof = (i + 2) * BK;
#pragma unroll
            for (int q = 0; q < 4; ++q) {
                rA[q][0] = *(const float4*)(srcA[q] + kof);
                rA[q][1] = *(const float4*)(srcA[q] + kof + 4);
            }
#pragma unroll
            for (int q = 0; q < 4; ++q)
                cp_async16(sbB + ((i + 2) % SB) * TILE_B16 + dstAB[q],
                           srcB[q] + kof);
        }
        cp_commit();

        const uint32_t aSlot = sbA + (uint32_t)((i & 1) * TILE_A16);
        const uint32_t bSlot = sbB + (uint32_t)((i % SB) * TILE_B16);
#pragma unroll
        for (int ks = 0; ks < 4; ++ks) {
            const uint32_t kx = (uint32_t)(ks << 5);
            uint32_t a[4][4];
#pragma unroll
            for (int mf = 0; mf < 4; ++mf)
                ldsm_x4(a[mf], (aSlot + aLdsm[mf]) ^ kx);
            uint32_t bf[4][4];
#pragma unroll
            for (int p = 0; p < 2; ++p)
                ldsm_x4(bf[p * 2], (bSlot + bLdsm[p]) ^ kx);
#pragma unroll
            for (int mf = 0; mf < 4; ++mf) {
#pragma unroll
                for (int p = 0; p < 2; ++p) {
                    mma_f16(c[mf][p * 2],     a[mf], &bf[p * 2][0]);
                    mma_f16(c[mf][p * 2 + 1], a[mf], &bf[p * 2][2]);
                }
            }
        }
    }

    // ======================= fused epilogue =======================
    cp_wait<0>();             // stat/We/Wc prefetch certainly done
    __syncthreads();          // all mainloop smem reads finished

    // ---- store C (fp16) into oH: row stride 272 B ----
#pragma unroll
    for (int mf = 0; mf < 4; ++mf) {
        const int row = wm + mf * 16 + lr;
#pragma unroll
        for (int nb = 0; nb < 4; ++nb) {
            const int col = wn + nb * 8 + lc * 2;
            sts_u32(sb + oH + row * 272 + col * 2,
                    pack_h2(c[mf][nb][0], c[mf][nb][1]));
            sts_u32(sb + oH + (row + 8) * 272 + col * 2,
                    pack_h2(c[mf][nb][2], c[mf][nb][3]));
        }
    }
    __syncthreads();

    // warp tile for the small gemms: rows 128 (2 warp-rows), cols 64 (4 warp-cols)
    const int wm2 = (warp >> 2) * 64;
    const int wn2 = (warp & 3) * 16;
    const uint32_t lcx = (uint32_t)(lc * 4);

    // ---- gemm1: code = H @ WcT (K = 128) ----
    float c1[4][2][4];
#pragma unroll
    for (int mf = 0; mf < 4; ++mf)
#pragma unroll
        for (int nb = 0; nb < 2; ++nb)
#pragma unroll
            for (int r = 0; r < 4; ++r) c1[mf][nb][r] = 0.0f;
#pragma unroll
    for (int ks = 0; ks < 8; ++ks) {
        const uint32_t ko = (uint32_t)(ks * 32);
        uint32_t a[4][4];
#pragma unroll
        for (int mf = 0; mf < 4; ++mf) {
            const uint32_t ad = sb + oH + (uint32_t)((wm2 + mf * 16 + lr) * 272) + ko + lcx;
            a[mf][0] = lds_u32(ad);
            a[mf][1] = lds_u32(ad + 8 * 272);
            a[mf][2] = lds_u32(ad + 16);
            a[mf][3] = lds_u32(ad + 8 * 272 + 16);
        }
        uint32_t bf[2][2];
#pragma unroll
        for (int nb = 0; nb < 2; ++nb) {
            const uint32_t bd = sb + oWc + (uint32_t)((wn2 + nb * 8 + lr) * 272) + ko + lcx;
            bf[nb][0] = lds_u32(bd);
            bf[nb][1] = lds_u32(bd + 16);
        }
#pragma unroll
        for (int mf = 0; mf < 4; ++mf)
#pragma unroll
            for (int nb = 0; nb < 2; ++nb)
                mma_f16(c1[mf][nb], a[mf], bf[nb]);
    }

    // ---- gemm2: gate = stat @ WeT (K = 256) ----
    float c2[4][2][4];
#pragma unroll
    for (int mf = 0; mf < 4; ++mf)
#pragma unroll
        for (int nb = 0; nb < 2; ++nb)
#pragma unroll
            for (int r = 0; r < 4; ++r) c2[mf][nb][r] = 0.0f;
#pragma unroll
    for (int ks = 0; ks < 16; ++ks) {
        const uint32_t ko = (uint32_t)(ks * 32);
        uint32_t a[4][4];
#pragma unroll
        for (int mf = 0; mf < 4; ++mf) {
            const uint32_t ad = sb + oS + (uint32_t)((wm2 + mf * 16 + lr) * 528) + ko + lcx;
            a[mf][0] = lds_u32(ad);
            a[mf][1] = lds_u32(ad + 8 * 528);
            a[mf][2] = lds_u32(ad + 16);
            a[mf][3] = lds_u32(ad + 8 * 528 + 16);
        }
        uint32_t bf[2][2];
#pragma unroll
        for (int nb = 0; nb < 2; ++nb) {
            const uint32_t bd = sb + oWe + (uint32_t)((wn2 + nb * 8 + lr) * 528) + ko + lcx;
            bf[nb][0] = lds_u32(bd);
            bf[nb][1] = lds_u32(bd + 16);
        }
#pragma unroll
        for (int mf = 0; mf < 4; ++mf)
#pragma unroll
            for (int nb = 0; nb < 2; ++nb)
                mma_f16(c2[mf][nb], a[mf], bf[nb]);
    }

    // ---- combine + store ----
    const float* bc = mat ? bbv : bfv;
#pragma unroll
    for (int nb = 0; nb < 2; ++nb) {
        const int cl = wn2 + nb * 8 + lc * 2;
        const float2 biasC = *(const float2*)(bc + cl);
        const float2 biasG = *(const float2*)(be + mat * 64 + cl);
#pragma unroll
        for (int mf = 0; mf < 4; ++mf) {
#pragma unroll
            for (int h = 0; h < 2; ++h) {
                const int row = r0g + wm2 + mf * 16 + lr + h * 8;
                const float2 dyn = *(const float2*)(nfeat + (size_t)row * kINPUT + cl);
                const float g0 = 1.0f / (1.0f + __expf(-(c2[mf][nb][2 * h]     + biasG.x)));
                const float g1 = 1.0f / (1.0f + __expf(-(c2[mf][nb][2 * h + 1] + biasG.y)));
                float2 o;
                o.x = (c1[mf][nb][2 * h]     + biasC.x) * dyn.x * g0;
                o.y = (c1[mf][nb][2 * h + 1] + biasC.y) * dyn.y * g1;
                *(float2*)(out + (size_t)row * 128 + mat * 64 + cl) = o;
            }
        }
    }
}

// ---------------------------------------------------------------------------
extern "C" void kernel_launch(void* const* d_in, const int* in_sizes, int n_in,
                              void* d_out, int out_size) {
    (void)in_sizes; (void)n_in; (void)out_size;
    const float* nfeat = (const float*)d_in[0];
    const float* adjF  = (const float*)d_in[1];
    const float* adjB  = (const float*)d_in[2];
    const float* Wf    = (const float*)d_in[3];
    const float* bfv   = (const float*)d_in[4];
    const float* Wb    = (const float*)d_in[5];
    const float* bbv   = (const float*)d_in[6];
    const float* We    = (const float*)d_in[7];
    const float* be    = (const float*)d_in[8];
    float* out = (float*)d_out;

    static bool attr_set = false;
    if (!attr_set) {
        cudaFuncSetAttribute(fused_kernel,
                             cudaFuncAttributeMaxDynamicSharedMemorySize, SMEM_TOTAL);
        attr_set = true;
    }

    prep_all<<<1536, 256>>>(nfeat, Wf, Wb, We);
    fused_kernel<<<dim3(kN / BM, kB, 2), 256, SMEM_TOTAL>>>(
        adjF, adjB, nfeat, bfv, bbv, be, out);
}

// round 11
// speedup vs baseline: 1.2988x; 1.2988x over previous
#include <cuda_runtime.h>
#include <cuda_fp16.h>
#include <cstdint>
#include <cstddef>

// ===========================================================================
// feature_embedding on GB300 (base compute_103: mma.sync fp16 tensor cores).
// Round 11: round-9 structure (best) + single prep launch + pipelined
// epilogue loads. gcn mainloop untouched (measured at fallback-HMMA floor).
//  B=4, N=2048, DEST=64, NET=256, INPUT=448
// ===========================================================================

namespace {
constexpr int kB     = 4;
constexpr int kN     = 2048;
constexpr int kINPUT = 448;
constexpr int BM     = 128;
constexpr int BK     = 64;           // k per iter (4 x m16n8k16)
constexpr int SB     = 3;            // B cp.async stages
constexpr int NUM_K  = kN / BK;      // 32
constexpr int TILE_A16 = BM * BK * 2;            // 16 KB fp16 A tile
constexpr int TILE_B16 = 128 * BK * 2;           // 16 KB fp16 B tile
constexpr int A_REGION = 2 * TILE_A16;           // A double buffer 32 KB
constexpr int SMEM_GCN = A_REGION + SB * TILE_B16;   // 80 KB

// epilogue smem layout (bytes) — 64-row tiles
constexpr int oH  = 0;            // H16 tile  64 x 272B
constexpr int oWc = 17408;        // WcT       64 x 272B
constexpr int oS  = 34816;        // stat16    64 x 528B
constexpr int oWe = 68608;        // WeT slice 64 x 528B
constexpr int SMEM_EPI = 102400;
}

// scratch
__device__ __align__(1024) __half g_Bt    [(size_t)kB * 128 * kN];  // structT fp16
__device__ __align__(1024) __half g_H16   [(size_t)kB * kN * 256];  // [hf|hb] fp16
__device__ __align__(1024) __half g_stat16[(size_t)kB * kN * 256];  // stat fp16
__device__ __align__(256)  __half g_WcT   [2 * 64 * 128];           // [mat][n][k]
__device__ __align__(256)  __half g_WeT   [128 * 256];              // [n][k]

// ---------------------------------------------------------------------------
// helpers
// ---------------------------------------------------------------------------
__device__ __forceinline__ uint32_t smem_u32(const void* p) {
    uint32_t a;
    asm("{ .reg .u64 t; cvta.to.shared.u64 t, %1; cvt.u32.u64 %0, t; }"
        : "=r"(a) : "l"(p));
    return a;
}
__device__ __forceinline__ void cp_async16(uint32_t dst, const void* src) {
    asm volatile("cp.async.cg.shared.global [%0], [%1], 16;"
                 :: "r"(dst), "l"(src) : "memory");
}
__device__ __forceinline__ void cp_commit() {
    asm volatile("cp.async.commit_group;" ::: "memory");
}
template <int N>
__device__ __forceinline__ void cp_wait() {
    asm volatile("cp.async.wait_group %0;" :: "n"(N) : "memory");
}
__device__ __forceinline__ uint32_t lds_u32(uint32_t addr) {
    uint32_t v;
    asm volatile("ld.shared.b32 %0, [%1];" : "=r"(v) : "r"(addr));
    return v;
}
__device__ __forceinline__ void ldsm_x4(uint32_t r[4], uint32_t addr) {
    asm volatile("ldmatrix.sync.aligned.m8n8.x4.shared.b16 {%0,%1,%2,%3}, [%4];"
                 : "=r"(r[0]), "=r"(r[1]), "=r"(r[2]), "=r"(r[3]) : "r"(addr));
}
__device__ __forceinline__ void sts_v4(uint32_t addr, uint32_t x, uint32_t y,
                                       uint32_t z, uint32_t w) {
    asm volatile("st.shared.v4.b32 [%0], {%1,%2,%3,%4};"
                 :: "r"(addr), "r"(x), "r"(y), "r"(z), "r"(w) : "memory");
}
__device__ __forceinline__ uint32_t pack_h2(float lo, float hi) {
    __half2 h = __floats2half2_rn(lo, hi);
    return *reinterpret_cast<uint32_t*>(&h);
}
__device__ __forceinline__ void mma_f16(float c[4], const uint32_t a[4],
                                        const uint32_t b[2]) {
    asm volatile(
        "mma.sync.aligned.m16n8k16.row.col.f32.f16.f16.f32 "
        "{%0,%1,%2,%3}, {%4,%5,%6,%7}, {%8,%9}, {%0,%1,%2,%3};"
        : "+f"(c[0]), "+f"(c[1]), "+f"(c[2]), "+f"(c[3])
        : "r"(a[0]), "r"(a[1]), "r"(a[2]), "r"(a[3]), "r"(b[0]), "r"(b[1]));
}

// ---------------------------------------------------------------------------
// Prep (single launch): blocks [0,1024) transpose struct -> g_Bt fp16;
// blocks [1024,1536) convert stat + weights.
// ---------------------------------------------------------------------------
__global__ void __launch_bounds__(256) prep_all(
    const float* __restrict__ nfeat,
    const float* __restrict__ Wf, const float* __restrict__ Wb,
    const float* __restrict__ We) {
    const int bx = blockIdx.x;
    if (bx < 1024) {
        __shared__ float t[32][33];
        const int b  = bx >> 8;
        const int f0 = ((bx >> 6) & 3) * 32;
        const int n0 = (bx & 63) * 32;
        const int tx = threadIdx.x & 31;
        const int ty = threadIdx.x >> 5;
#pragma unroll
        for (int j = 0; j < 32; j += 8)
            t[ty + j][tx] = nfeat[((size_t)(b * kN + n0 + ty + j)) * kINPUT + 64 + f0 + tx];
        __syncthreads();
#pragma unroll
        for (int j = 0; j < 32; j += 8)
            g_Bt[((size_t)b * 128 + f0 + ty + j) * kN + n0 + tx] =
                __float2half_rn(t[tx][ty + j]);
    } else {
        const int t = (bx - 1024) * 256 + threadIdx.x;   // 0..131071
        for (int i = t; i < kB * kN * 64; i += 131072) { // stat fp32 -> fp16
            const int row = i >> 6, c4 = i & 63;
            const float4 v = *(const float4*)(nfeat + (size_t)row * kINPUT + 192 + c4 * 4);
            uint32_t* d = reinterpret_cast<uint32_t*>(g_stat16 + (size_t)row * 256 + c4 * 4);
            d[0] = pack_h2(v.x, v.y);
            d[1] = pack_h2(v.z, v.w);
        }
        if (t < 128 * 256) {      // WeT
            const int n = t >> 8, k = t & 255;
            g_WeT[t] = __float2half_rn(We[k * 128 + n]);
        }
        if (t < 64 * 128) {       // WcT (both mats)
            const int n = t >> 7, k = t & 127;
            g_WcT[t]        = __float2half_rn(Wf[k * 64 + n]);
            g_WcT[8192 + t] = __float2half_rn(Wb[k * 64 + n]);
        }
    }
}

// ---------------------------------------------------------------------------
// Kernel A: H16-tile[128,128] = adj_tile[128,2048] @ structT[128,2048]^T
// grid (16, 4, 2); 256 threads (8 warps). BK=64: 32 iterations.
// Fragment loads via ldmatrix.x4 (conflict-free under vec^row&7 swizzle).
// (UNCHANGED from round 9 — measured at the fallback-HMMA issue floor.)
// ---------------------------------------------------------------------------
__global__ void __launch_bounds__(256, 1) gcn_mma_kernel(
    const float* __restrict__ adjF, const float* __restrict__ adjB) {
    extern __shared__ char smem[];
    const uint32_t sbA = smem_u32(smem);                 // A16: 2 x 16 KB
    const uint32_t sbB = sbA + A_REGION;                 // B16: 3 x 16 KB

    const int tid  = threadIdx.x;
    const int warp = tid >> 5;
    const int lane = tid & 31;
    const int lr   = lane >> 2;
    const int lc   = lane & 3;
    const int wm   = (warp >> 2) * 64;
    const int wn   = (warp & 3) * 32;

    const int m0  = blockIdx.x * BM;
    const int b   = blockIdx.y;
    const int mat = blockIdx.z;
    const float* adj = mat ? adjB : adjF;

    const float*  srcA[4];
    const __half* srcB[4];
    uint32_t dstAB[4];
#pragma unroll
    for (int q = 0; q < 4; ++q) {
        const int idx = q * 256 + tid;
        const int row = idx >> 3;
        const int vec = idx & 7;
        srcA[q] = adj  + ((size_t)(b * kN + m0 + row)) * kN + vec * 8;
        srcB[q] = g_Bt + ((size_t)(b * 128 + row)) * kN + vec * 8;
        dstAB[q] = (uint32_t)(row * 128 + ((vec ^ (row & 7)) << 4));
    }

    const int g  = lane >> 3;
    const int tr = lane & 7;
    uint32_t aLdsm[4];
#pragma unroll
    for (int mf = 0; mf < 4; ++mf) {
        const int row = wm + mf * 16 + (g & 1) * 8 + tr;
        aLdsm[mf] = (uint32_t)(row * 128 + (((g >> 1) ^ (row & 7)) << 4));
    }
    uint32_t bLdsm[2];
#pragma unroll
    for (int p = 0; p < 2; ++p) {
        const int row = wn + p * 16 + (g >> 1) * 8 + tr;
        bLdsm[p] = (uint32_t)(row * 128 + (((g & 1) ^ (row & 7)) << 4));
    }

    float c[4][4][4];
#pragma unroll
    for (int mf = 0; mf < 4; ++mf)
#pragma unroll
        for (int nb = 0; nb < 4; ++nb)
#pragma unroll
            for (int r = 0; r < 4; ++r) c[mf][nb][r] = 0.0f;

#pragma unroll
    for (int s = 0; s < SB - 1; ++s) {
#pragma unroll
        for (int q = 0; q < 4; ++q)
            cp_async16(sbB + s * TILE_B16 + dstAB[q], srcB[q] + s * BK);
        cp_commit();
    }
    float4 rA[4][2];
#pragma unroll
    for (int q = 0; q < 4; ++q) {
        rA[q][0] = *(const float4*)(srcA[q]);
        rA[q][1] = *(const float4*)(srcA[q] + 4);
    }
#pragma unroll
    for (int q = 0; q < 4; ++q)
        sts_v4(sbA + dstAB[q],
               pack_h2(rA[q][0].x, rA[q][0].y), pack_h2(rA[q][0].z, rA[q][0].w),
               pack_h2(rA[q][1].x, rA[q][1].y), pack_h2(rA[q][1].z, rA[q][1].w));
#pragma unroll
    for (int q = 0; q < 4; ++q) {
        rA[q][0] = *(const float4*)(srcA[q] + BK);
        rA[q][1] = *(const float4*)(srcA[q] + BK + 4);
    }

    for (int i = 0; i < NUM_K; ++i) {
        cp_wait<SB - 2>();
        __syncthreads();

        if (i + 1 < NUM_K) {
            const uint32_t aNext = sbA + (uint32_t)(((i + 1) & 1) * TILE_A16);
#pragma unroll
            for (int q = 0; q < 4; ++q)
                sts_v4(aNext + dstAB[q],
                       pack_h2(rA[q][0].x, rA[q][0].y), pack_h2(rA[q][0].z, rA[q][0].w),
                       pack_h2(rA[q][1].x, rA[q][1].y), pack_h2(rA[q][1].z, rA[q][1].w));
        }
        if (i + 2 < NUM_K) {
            const int kof = (i + 2) * BK;
#pragma unroll
            for (int q = 0; q < 4; ++q) {
                rA[q][0] = *(const float4*)(srcA[q] + kof);
                rA[q][1] = *(const float4*)(srcA[q] + kof + 4);
            }
#pragma unroll
            for (int q = 0; q < 4; ++q)
                cp_async16(sbB + ((i + 2) % SB) * TILE_B16 + dstAB[q],
                           srcB[q] + kof);
        }
        cp_commit();

        const uint32_t aSlot = sbA + (uint32_t)((i & 1) * TILE_A16);
        const uint32_t bSlot = sbB + (uint32_t)((i % SB) * TILE_B16);
#pragma unroll
        for (int ks = 0; ks < 4; ++ks) {
            const uint32_t kx = (uint32_t)(ks << 5);
            uint32_t a[4][4];
#pragma unroll
            for (int mf = 0; mf < 4; ++mf)
                ldsm_x4(a[mf], (aSlot + aLdsm[mf]) ^ kx);
            uint32_t bf[4][4];
#pragma unroll
            for (int p = 0; p < 2; ++p)
                ldsm_x4(bf[p * 2], (bSlot + bLdsm[p]) ^ kx);
#pragma unroll
            for (int mf = 0; mf < 4; ++mf) {
#pragma unroll
                for (int p = 0; p < 2; ++p) {
                    mma_f16(c[mf][p * 2],     a[mf], &bf[p * 2][0]);
                    mma_f16(c[mf][p * 2 + 1], a[mf], &bf[p * 2][2]);
                }
            }
        }
    }

#pragma unroll
    for (int mf = 0; mf < 4; ++mf) {
        const int row = m0 + wm + mf * 16 + lr;
        const size_t base = ((size_t)(b * kN + row)) * 256 + mat * 128;
#pragma unroll
        for (int nb = 0; nb < 4; ++nb) {
            const int col = wn + nb * 8 + lc * 2;
            *reinterpret_cast<uint32_t*>(g_H16 + base + col) =
                pack_h2(c[mf][nb][0], c[mf][nb][1]);
            *reinterpret_cast<uint32_t*>(g_H16 + base + 8 * 256 + col) =
                pack_h2(c[mf][nb][2], c[mf][nb][3]);
        }
    }
}

// ---------------------------------------------------------------------------
// Kernel B: mma epilogue. grid (128, 2) = (row-tile of 64, mat); 256 threads;
// 2 CTAs/SM. Loads pipelined in TWO cp.async groups:
//   group1 = H16 + WcT  -> wait<1> -> gemm1 (code) overlaps group2 transfer
//   group2 = stat + WeT -> wait<0> -> gemm2 (gate), combine, store.
// ---------------------------------------------------------------------------
__global__ void __launch_bounds__(256, 2) epilogue_mma(
    const float* __restrict__ nfeat,
    const float* __restrict__ bfv, const float* __restrict__ bbv,
    const float* __restrict__ be,  float* __restrict__ out) {
    extern __shared__ char smem[];
    const uint32_t sb = smem_u32(smem);

    const int tid  = threadIdx.x;
    const int warp = tid >> 5;
    const int lane = tid & 31;
    const int lr   = lane >> 2;
    const int lc   = lane & 3;
    const int wm   = (warp >> 2) * 32;   // rows 0 | 32
    const int wn   = (warp & 3) * 16;    // cols (0..63)

    const int r0  = blockIdx.x * 64;     // global row in [0, 8192)
    const int mat = blockIdx.y;

    // ---- group 1: H16 + WcT ----
    for (int idx = tid; idx < 1024; idx += 256) {        // H16 slice 64x128
        const int row = idx >> 4, v = idx & 15;
        cp_async16(sb + oH + row * 272 + v * 16,
                   g_H16 + ((size_t)(r0 + row)) * 256 + mat * 128 + v * 8);
    }
    for (int idx = tid; idx < 1024; idx += 256) {        // WcT 64x128
        const int row = idx >> 4, v = idx & 15;
        cp_async16(sb + oWc + row * 272 + v * 16,
                   g_WcT + mat * 64 * 128 + row * 128 + v * 8);
    }
    cp_commit();
    // ---- group 2: stat16 + WeT ----
    for (int idx = tid; idx < 2048; idx += 256) {        // stat16 64x256
        const int row = idx >> 5, v = idx & 31;
        cp_async16(sb + oS + row * 528 + v * 16,
                   g_stat16 + ((size_t)(r0 + row)) * 256 + v * 8);
    }
    for (int idx = tid; idx < 2048; idx += 256) {        // WeT slice 64x256
        const int row = idx >> 5, v = idx & 31;
        cp_async16(sb + oWe + row * 528 + v * 16,
                   g_WeT + ((size_t)(mat * 64 + row)) * 256 + v * 8);
    }
    cp_commit();

    cp_wait<1>();             // group 1 done; group 2 still in flight
    __syncthreads();

    const uint32_t lcx = (uint32_t)(lc * 4);

    // ---- gemm1: code (K = 128) — overlaps group-2 transfer ----
    float c1[2][2][4];
#pragma unroll
    for (int mf = 0; mf < 2; ++mf)
#pragma unroll
        for (int nb = 0; nb < 2; ++nb)
#pragma unroll
            for (int r = 0; r < 4; ++r) c1[mf][nb][r] = 0.0f;
#pragma unroll
    for (int ks = 0; ks < 8; ++ks) {
        const uint32_t ko = (uint32_t)(ks * 32);
        uint32_t a[2][4];
#pragma unroll
        for (int mf = 0; mf < 2; ++mf) {
            const uint32_t ad = sb + oH + (uint32_t)((wm + mf * 16 + lr) * 272) + ko + lcx;
            a[mf][0] = lds_u32(ad);
            a[mf][1] = lds_u32(ad + 8 * 272);
            a[mf][2] = lds_u32(ad + 16);
            a[mf][3] = lds_u32(ad + 8 * 272 + 16);
        }
        uint32_t bf[2][2];
#pragma unroll
        for (int nb = 0; nb < 2; ++nb) {
            const uint32_t bd = sb + oWc + (uint32_t)((wn + nb * 8 + lr) * 272) + ko + lcx;
            bf[nb][0] = lds_u32(bd);
            bf[nb][1] = lds_u32(bd + 16);
        }
#pragma unroll
        for (int mf = 0; mf < 2; ++mf)
#pragma unroll
            for (int nb = 0; nb < 2; ++nb)
                mma_f16(c1[mf][nb], a[mf], bf[nb]);
    }

    cp_wait<0>();             // group 2 done
    __syncthreads();

    // ---- gemm2: gate (K = 256) ----
    float c2[2][2][4];
#pragma unroll
    for (int mf = 0; mf < 2; ++mf)
#pragma unroll
        for (int nb = 0; nb < 2; ++nb)
#pragma unroll
            for (int r = 0; r < 4; ++r) c2[mf][nb][r] = 0.0f;
#pragma unroll
    for (int ks = 0; ks < 16; ++ks) {
        const uint32_t ko = (uint32_t)(ks * 32);
        uint32_t a[2][4];
#pragma unroll
        for (int mf = 0; mf < 2; ++mf) {
            const uint32_t ad = sb + oS + (uint32_t)((wm + mf * 16 + lr) * 528) + ko + lcx;
            a[mf][0] = lds_u32(ad);
            a[mf][1] = lds_u32(ad + 8 * 528);
            a[mf][2] = lds_u32(ad + 16);
            a[mf][3] = lds_u32(ad + 8 * 528 + 16);
        }
        uint32_t bf[2][2];
#pragma unroll
        for (int nb = 0; nb < 2; ++nb) {
            const uint32_t bd = sb + oWe + (uint32_t)((wn + nb * 8 + lr) * 528) + ko + lcx;
            bf[nb][0] = lds_u32(bd);
            bf[nb][1] = lds_u32(bd + 16);
        }
#pragma unroll
        for (int mf = 0; mf < 2; ++mf)
#pragma unroll
            for (int nb = 0; nb < 2; ++nb)
                mma_f16(c2[mf][nb], a[mf], bf[nb]);
    }

    // ---- combine + store ----
    const float* bc = mat ? bbv : bfv;
#pragma unroll
    for (int nb = 0; nb < 2; ++nb) {
        const int cl = wn + nb * 8 + lc * 2;
        const float2 biasC = *(const float2*)(bc + cl);
        const float2 biasG = *(const float2*)(be + mat * 64 + cl);
#pragma unroll
        for (int mf = 0; mf < 2; ++mf) {
#pragma unroll
            for (int h = 0; h < 2; ++h) {
                const int row = r0 + wm + mf * 16 + lr + h * 8;
                const float2 dyn = *(const float2*)(nfeat + (size_t)row * kINPUT + cl);
                const float g0 = 1.0f / (1.0f + __expf(-(c2[mf][nb][2 * h]     + biasG.x)));
                const float g1 = 1.0f / (1.0f + __expf(-(c2[mf][nb][2 * h + 1] + biasG.y)));
                float2 o;
                o.x = (c1[mf][nb][2 * h]     + biasC.x) * dyn.x * g0;
                o.y = (c1[mf][nb][2 * h + 1] + biasC.y) * dyn.y * g1;
                *(float2*)(out + (size_t)row * 128 + mat * 64 + cl) = o;
            }
        }
    }
}

// ---------------------------------------------------------------------------
extern "C" void kernel_launch(void* const* d_in, const int* in_sizes, int n_in,
                              void* d_out, int out_size) {
    (void)in_sizes; (void)n_in; (void)out_size;
    const float* nfeat = (const float*)d_in[0];
    const float* adjF  = (const float*)d_in[1];
    const float* adjB  = (const float*)d_in[2];
    const float* Wf    = (const float*)d_in[3];
    const float* bfv   = (const float*)d_in[4];
    const float* Wb    = (const float*)d_in[5];
    const float* bbv   = (const float*)d_in[6];
    const float* We    = (const float*)d_in[7];
    const float* be    = (const float*)d_in[8];
    float* out = (float*)d_out;

    static bool attr_set = false;
    if (!attr_set) {
        cudaFuncSetAttribute(gcn_mma_kernel,
                             cudaFuncAttributeMaxDynamicSharedMemorySize, SMEM_GCN);
        cudaFuncSetAttribute(epilogue_mma,
                             cudaFuncAttributeMaxDynamicSharedMemorySize, SMEM_EPI);
        attr_set = true;
    }

    prep_all<<<1536, 256>>>(nfeat, Wf, Wb, We);
    gcn_mma_kernel<<<dim3(kN / BM, kB, 2), 256, SMEM_GCN>>>(adjF, adjB);
    epilogue_mma<<<dim3(kB * kN / 64, 2), 256, SMEM_EPI>>>(nfeat, bfv, bbv, be, out);
}